// round 1
// baseline (speedup 1.0000x reference)
#include <cuda_runtime.h>
#include <math.h>

#define BSZ 16384
#define DM  512
#define NHD 4
#define KD  128
#define EPSLN 1e-6f

// ---------------- scratch (device globals; no allocs allowed) ----------------
__device__ float g_fp[BSZ * DM];
__device__ float g_rp[BSZ * DM];
__device__ float g_mp[BSZ * DM];
__device__ float g_h [BSZ * 256];
__device__ float g_aw[BSZ * 3];
__device__ float g_q [BSZ * 3 * DM];
__device__ float g_k [BSZ * 3 * DM];
__device__ float g_v [BSZ * 3 * DM];
__device__ float g_ctx[BSZ * 3 * DM];
__device__ float g_o [BSZ * 3 * DM];
__device__ float g_wt[BSZ * DM];
__device__ float g_gl[BSZ * DM];

// ---------------- SGEMM core: 128x128 tile, BK=8, 256 threads, 8x8/thread ----
template <int RELU>
__device__ __forceinline__ void gemm_core(
    const float* __restrict__ A, int lda,
    const float* __restrict__ Bm, int ldb,
    const float* __restrict__ bias,
    float* __restrict__ C, int ldc, int Kdim)
{
    __shared__ float As[8][128];
    __shared__ float Bs[8][128];
    const int tid = threadIdx.x;
    const int m0 = blockIdx.y * 128;
    const int n0 = blockIdx.x * 128;
    const int ar = tid >> 1, ac = (tid & 1) << 2;
    const int br = tid >> 5, bc = (tid & 31) << 2;
    const int ty = tid >> 4, tx = tid & 15;

    float acc[8][8];
#pragma unroll
    for (int i = 0; i < 8; i++)
#pragma unroll
        for (int j = 0; j < 8; j++) acc[i][j] = 0.f;

    const float* Aptr = A + (size_t)(m0 + ar) * lda + ac;
    const float* Bptr = Bm + (size_t)br * ldb + n0 + bc;

    for (int k0 = 0; k0 < Kdim; k0 += 8) {
        float4 av = *reinterpret_cast<const float4*>(Aptr + k0);
        float4 bv = *reinterpret_cast<const float4*>(Bptr + (size_t)k0 * ldb);
        As[ac + 0][ar] = av.x; As[ac + 1][ar] = av.y;
        As[ac + 2][ar] = av.z; As[ac + 3][ar] = av.w;
        *reinterpret_cast<float4*>(&Bs[br][bc]) = bv;
        __syncthreads();
#pragma unroll
        for (int kk = 0; kk < 8; kk++) {
            float4 a0 = *reinterpret_cast<const float4*>(&As[kk][ty * 8]);
            float4 a1 = *reinterpret_cast<const float4*>(&As[kk][ty * 8 + 4]);
            float4 b0 = *reinterpret_cast<const float4*>(&Bs[kk][tx * 8]);
            float4 b1 = *reinterpret_cast<const float4*>(&Bs[kk][tx * 8 + 4]);
            float a[8] = {a0.x, a0.y, a0.z, a0.w, a1.x, a1.y, a1.z, a1.w};
            float b[8] = {b0.x, b0.y, b0.z, b0.w, b1.x, b1.y, b1.z, b1.w};
#pragma unroll
            for (int i = 0; i < 8; i++)
#pragma unroll
                for (int j = 0; j < 8; j++) acc[i][j] = fmaf(a[i], b[j], acc[i][j]);
        }
        __syncthreads();
    }
#pragma unroll
    for (int i = 0; i < 8; i++) {
        float* Crow = C + (size_t)(m0 + ty * 8 + i) * ldc + n0 + tx * 8;
#pragma unroll
        for (int j = 0; j < 8; j += 4) {
            const float* bp = bias + n0 + tx * 8 + j;
            float4 r;
            r.x = acc[i][j + 0] + bp[0];
            r.y = acc[i][j + 1] + bp[1];
            r.z = acc[i][j + 2] + bp[2];
            r.w = acc[i][j + 3] + bp[3];
            if (RELU) {
                r.x = fmaxf(r.x, 0.f); r.y = fmaxf(r.y, 0.f);
                r.z = fmaxf(r.z, 0.f); r.w = fmaxf(r.w, 0.f);
            }
            *reinterpret_cast<float4*>(Crow + j) = r;
        }
    }
}

// ---------------- kernels ----------------
__global__ __launch_bounds__(256, 2)
void k_proj(const float* __restrict__ f, const float* __restrict__ r,
            const float* __restrict__ m,
            const float* __restrict__ Wf, const float* __restrict__ bf,
            const float* __restrict__ Wr, const float* __restrict__ br2,
            const float* __restrict__ Wm, const float* __restrict__ bm)
{
    int z = blockIdx.z;
    const float* A  = (z == 0) ? f  : (z == 1) ? r   : m;
    const float* W  = (z == 0) ? Wf : (z == 1) ? Wr  : Wm;
    const float* bb = (z == 0) ? bf : (z == 1) ? br2 : bm;
    float* C        = (z == 0) ? g_fp : (z == 1) ? g_rp : g_mp;
    gemm_core<0>(A, 512, W, 512, bb, C, 512, 512);
}

// h = relu(concat(fp,rp,mp) @ Wa1 + ba1)   [B,1536]x[1536,256]
__global__ __launch_bounds__(256, 2)
void k_h(const float* __restrict__ Wa1, const float* __restrict__ ba1)
{
    __shared__ float As[8][128];
    __shared__ float Bs[8][128];
    const int tid = threadIdx.x;
    const int m0 = blockIdx.y * 128;
    const int n0 = blockIdx.x * 128;
    const int ar = tid >> 1, ac = (tid & 1) << 2;
    const int br = tid >> 5, bc = (tid & 31) << 2;
    const int ty = tid >> 4, tx = tid & 15;

    float acc[8][8];
#pragma unroll
    for (int i = 0; i < 8; i++)
#pragma unroll
        for (int j = 0; j < 8; j++) acc[i][j] = 0.f;

    const float* Bptr = Wa1 + (size_t)br * 256 + n0 + bc;

    for (int k0 = 0; k0 < 1536; k0 += 8) {
        int g = k0 + ac;
        int seg = g >> 9;
        int lc  = g & 511;
        const float* Aseg = (seg == 0) ? g_fp : (seg == 1) ? g_rp : g_mp;
        float4 av = *reinterpret_cast<const float4*>(Aseg + (size_t)(m0 + ar) * 512 + lc);
        float4 bv = *reinterpret_cast<const float4*>(Bptr + (size_t)k0 * 256);
        As[ac + 0][ar] = av.x; As[ac + 1][ar] = av.y;
        As[ac + 2][ar] = av.z; As[ac + 3][ar] = av.w;
        *reinterpret_cast<float4*>(&Bs[br][bc]) = bv;
        __syncthreads();
#pragma unroll
        for (int kk = 0; kk < 8; kk++) {
            float4 a0 = *reinterpret_cast<const float4*>(&As[kk][ty * 8]);
            float4 a1 = *reinterpret_cast<const float4*>(&As[kk][ty * 8 + 4]);
            float4 b0 = *reinterpret_cast<const float4*>(&Bs[kk][tx * 8]);
            float4 b1 = *reinterpret_cast<const float4*>(&Bs[kk][tx * 8 + 4]);
            float a[8] = {a0.x, a0.y, a0.z, a0.w, a1.x, a1.y, a1.z, a1.w};
            float b[8] = {b0.x, b0.y, b0.z, b0.w, b1.x, b1.y, b1.z, b1.w};
#pragma unroll
            for (int i = 0; i < 8; i++)
#pragma unroll
                for (int j = 0; j < 8; j++) acc[i][j] = fmaf(a[i], b[j], acc[i][j]);
        }
        __syncthreads();
    }
#pragma unroll
    for (int i = 0; i < 8; i++) {
        float* Crow = g_h + (size_t)(m0 + ty * 8 + i) * 256 + n0 + tx * 8;
#pragma unroll
        for (int j = 0; j < 8; j += 4) {
            const float* bp = ba1 + n0 + tx * 8 + j;
            float4 r;
            r.x = fmaxf(acc[i][j + 0] + bp[0], 0.f);
            r.y = fmaxf(acc[i][j + 1] + bp[1], 0.f);
            r.z = fmaxf(acc[i][j + 2] + bp[2], 0.f);
            r.w = fmaxf(acc[i][j + 3] + bp[3], 0.f);
            *reinterpret_cast<float4*>(Crow + j) = r;
        }
    }
}

// aw = softmax(h @ Wa2 + ba2), one warp per row
__global__ __launch_bounds__(128)
void k_aw(const float* __restrict__ Wa2, const float* __restrict__ ba2)
{
    int row = blockIdx.x * 4 + (threadIdx.x >> 5);
    int l = threadIdx.x & 31;
    const float* hr = g_h + (size_t)row * 256;
    float a0 = 0.f, a1 = 0.f, a2 = 0.f;
#pragma unroll
    for (int i = l; i < 256; i += 32) {
        float hv = hr[i];
        a0 = fmaf(hv, Wa2[i * 3 + 0], a0);
        a1 = fmaf(hv, Wa2[i * 3 + 1], a1);
        a2 = fmaf(hv, Wa2[i * 3 + 2], a2);
    }
#pragma unroll
    for (int off = 16; off; off >>= 1) {
        a0 += __shfl_xor_sync(0xffffffffu, a0, off);
        a1 += __shfl_xor_sync(0xffffffffu, a1, off);
        a2 += __shfl_xor_sync(0xffffffffu, a2, off);
    }
    if (l == 0) {
        a0 += ba2[0]; a1 += ba2[1]; a2 += ba2[2];
        float mx = fmaxf(a0, fmaxf(a1, a2));
        float e0 = expf(a0 - mx), e1 = expf(a1 - mx), e2 = expf(a2 - mx);
        float inv = 1.f / (e0 + e1 + e2);
        g_aw[row * 3 + 0] = e0 * inv;
        g_aw[row * 3 + 1] = e1 * inv;
        g_aw[row * 3 + 2] = e2 * inv;
    }
}

__global__ __launch_bounds__(256, 2)
void k_qkv(const float* __restrict__ Wq, const float* __restrict__ bq,
           const float* __restrict__ Wk, const float* __restrict__ bk,
           const float* __restrict__ Wv, const float* __restrict__ bv)
{
    int z = blockIdx.z;
    int s = z / 3, w = z % 3;
    const float* A  = (s == 0) ? g_fp : (s == 1) ? g_rp : g_mp;
    const float* W  = (w == 0) ? Wq : (w == 1) ? Wk : Wv;
    const float* bb = (w == 0) ? bq : (w == 1) ? bk : bv;
    float* C = ((w == 0) ? g_q : (w == 1) ? g_k : g_v) + s * 512;
    gemm_core<0>(A, 512, W, 512, bb, C, 1536, 512);
}

__device__ __forceinline__ float d4(float4 a, float4 b)
{
    return a.x * b.x + a.y * b.y + a.z * b.z + a.w * b.w;
}

// attention over S=3: one block per row, one warp per head, all in registers
__global__ __launch_bounds__(128)
void k_attn()
{
    int b = blockIdx.x;
    int h = threadIdx.x >> 5;
    int l = threadIdx.x & 31;
    size_t base = (size_t)b * 1536 + h * 128 + l * 4;
    float4 q0 = *reinterpret_cast<const float4*>(&g_q[base]);
    float4 q1 = *reinterpret_cast<const float4*>(&g_q[base + 512]);
    float4 q2 = *reinterpret_cast<const float4*>(&g_q[base + 1024]);
    float4 k0 = *reinterpret_cast<const float4*>(&g_k[base]);
    float4 k1 = *reinterpret_cast<const float4*>(&g_k[base + 512]);
    float4 k2 = *reinterpret_cast<const float4*>(&g_k[base + 1024]);
    float4 v0 = *reinterpret_cast<const float4*>(&g_v[base]);
    float4 v1 = *reinterpret_cast<const float4*>(&g_v[base + 512]);
    float4 v2 = *reinterpret_cast<const float4*>(&g_v[base + 1024]);

    float sc[3][3];
    sc[0][0] = d4(q0, k0); sc[0][1] = d4(q0, k1); sc[0][2] = d4(q0, k2);
    sc[1][0] = d4(q1, k0); sc[1][1] = d4(q1, k1); sc[1][2] = d4(q1, k2);
    sc[2][0] = d4(q2, k0); sc[2][1] = d4(q2, k1); sc[2][2] = d4(q2, k2);
#pragma unroll
    for (int qi = 0; qi < 3; qi++)
#pragma unroll
        for (int si = 0; si < 3; si++)
#pragma unroll
            for (int off = 16; off; off >>= 1)
                sc[qi][si] += __shfl_xor_sync(0xffffffffu, sc[qi][si], off);

    const float scale = 0.088388347648318447f;  // 1/sqrt(128)
#pragma unroll
    for (int qi = 0; qi < 3; qi++) {
        float s0 = sc[qi][0] * scale, s1 = sc[qi][1] * scale, s2 = sc[qi][2] * scale;
        float mx = fmaxf(s0, fmaxf(s1, s2));
        float e0 = expf(s0 - mx), e1 = expf(s1 - mx), e2 = expf(s2 - mx);
        float inv = 1.f / (e0 + e1 + e2);
        float a0 = e0 * inv, a1 = e1 * inv, a2 = e2 * inv;
        float4 c;
        c.x = a0 * v0.x + a1 * v1.x + a2 * v2.x;
        c.y = a0 * v0.y + a1 * v1.y + a2 * v2.y;
        c.z = a0 * v0.z + a1 * v1.z + a2 * v2.z;
        c.w = a0 * v0.w + a1 * v1.w + a2 * v2.w;
        *reinterpret_cast<float4*>(&g_ctx[base + (size_t)qi * 512]) = c;
    }
}

__global__ __launch_bounds__(256, 2)
void k_o(const float* __restrict__ Wo, const float* __restrict__ bo)
{
    gemm_core<0>(g_ctx, 512, Wo, 512, bo, g_o, 512, 512);
}

__device__ __forceinline__ void block_reduce2(float& s, float& q, float* ss, float* sq)
{
#pragma unroll
    for (int off = 16; off; off >>= 1) {
        s += __shfl_xor_sync(0xffffffffu, s, off);
        q += __shfl_xor_sync(0xffffffffu, q, off);
    }
    int w = threadIdx.x >> 5;
    if ((threadIdx.x & 31) == 0) { ss[w] = s; sq[w] = q; }
    __syncthreads();
    s = ss[0] + ss[1] + ss[2] + ss[3];
    q = sq[0] + sq[1] + sq[2] + sq[3];
    __syncthreads();
}

// y_s = LN1(x_s + o_s); weighted = sum_s aw_s * y_s
__global__ __launch_bounds__(128)
void k_post1(const float* __restrict__ gamma1, const float* __restrict__ beta1)
{
    __shared__ float ss[4], sq[4];
    int b = blockIdx.x;
    int d = threadIdx.x * 4;
    float aw0 = g_aw[b * 3 + 0], aw1 = g_aw[b * 3 + 1], aw2 = g_aw[b * 3 + 2];
    float4 gm = *reinterpret_cast<const float4*>(&gamma1[d]);
    float4 be = *reinterpret_cast<const float4*>(&beta1[d]);
    float4 wacc = make_float4(0.f, 0.f, 0.f, 0.f);
#pragma unroll
    for (int s = 0; s < 3; s++) {
        const float* X = (s == 0) ? g_fp : (s == 1) ? g_rp : g_mp;
        float4 xv = *reinterpret_cast<const float4*>(&X[(size_t)b * 512 + d]);
        float4 ov = *reinterpret_cast<const float4*>(&g_o[((size_t)b * 3 + s) * 512 + d]);
        float4 v;
        v.x = xv.x + ov.x; v.y = xv.y + ov.y; v.z = xv.z + ov.z; v.w = xv.w + ov.w;
        float lsum = v.x + v.y + v.z + v.w;
        float lsq  = v.x * v.x + v.y * v.y + v.z * v.z + v.w * v.w;
        block_reduce2(lsum, lsq, ss, sq);
        float mean = lsum * (1.f / 512.f);
        float var  = lsq * (1.f / 512.f) - mean * mean;
        float inv  = rsqrtf(var + EPSLN);
        float a = (s == 0) ? aw0 : (s == 1) ? aw1 : aw2;
        wacc.x += a * (gm.x * (v.x - mean) * inv + be.x);
        wacc.y += a * (gm.y * (v.y - mean) * inv + be.y);
        wacc.z += a * (gm.z * (v.z - mean) * inv + be.z);
        wacc.w += a * (gm.w * (v.w - mean) * inv + be.w);
    }
    *reinterpret_cast<float4*>(&g_wt[(size_t)b * 512 + d]) = wacc;
}

__global__ __launch_bounds__(256, 2)
void k_gate(const float* __restrict__ Wg, const float* __restrict__ bg)
{
    gemm_core<0>(g_wt, 512, Wg, 512, bg, g_gl, 512, 512);
}

__device__ __forceinline__ float sigm(float x) { return 1.f / (1.f + expf(-x)); }

// out = LN2(mp + sigmoid(gl) * weighted)
__global__ __launch_bounds__(128)
void k_post2(const float* __restrict__ gamma2, const float* __restrict__ beta2,
             float* __restrict__ out)
{
    __shared__ float ss[4], sq[4];
    int b = blockIdx.x;
    int d = threadIdx.x * 4;
    float4 wv = *reinterpret_cast<const float4*>(&g_wt[(size_t)b * 512 + d]);
    float4 gl = *reinterpret_cast<const float4*>(&g_gl[(size_t)b * 512 + d]);
    float4 mp = *reinterpret_cast<const float4*>(&g_mp[(size_t)b * 512 + d]);
    float4 t;
    t.x = mp.x + sigm(gl.x) * wv.x;
    t.y = mp.y + sigm(gl.y) * wv.y;
    t.z = mp.z + sigm(gl.z) * wv.z;
    t.w = mp.w + sigm(gl.w) * wv.w;
    float lsum = t.x + t.y + t.z + t.w;
    float lsq  = t.x * t.x + t.y * t.y + t.z * t.z + t.w * t.w;
    block_reduce2(lsum, lsq, ss, sq);
    float mean = lsum * (1.f / 512.f);
    float var  = lsq * (1.f / 512.f) - mean * mean;
    float inv  = rsqrtf(var + EPSLN);
    float4 gm = *reinterpret_cast<const float4*>(&gamma2[d]);
    float4 be = *reinterpret_cast<const float4*>(&beta2[d]);
    float4 r;
    r.x = gm.x * (t.x - mean) * inv + be.x;
    r.y = gm.y * (t.y - mean) * inv + be.y;
    r.z = gm.z * (t.z - mean) * inv + be.z;
    r.w = gm.w * (t.w - mean) * inv + be.w;
    *reinterpret_cast<float4*>(&out[(size_t)b * 512 + d]) = r;
}

// ---------------- launch ----------------
extern "C" void kernel_launch(void* const* d_in, const int* in_sizes, int n_in,
                              void* d_out, int out_size)
{
    const float* frontier = (const float*)d_in[0];
    const float* cross    = (const float*)d_in[1];
    const float* mapf     = (const float*)d_in[2];
    const float* Wf  = (const float*)d_in[3];
    const float* bf  = (const float*)d_in[4];
    const float* Wr  = (const float*)d_in[5];
    const float* br  = (const float*)d_in[6];
    const float* Wm  = (const float*)d_in[7];
    const float* bm  = (const float*)d_in[8];
    const float* Wa1 = (const float*)d_in[9];
    const float* ba1 = (const float*)d_in[10];
    const float* Wa2 = (const float*)d_in[11];
    const float* ba2 = (const float*)d_in[12];
    const float* Wq  = (const float*)d_in[13];
    const float* bq  = (const float*)d_in[14];
    const float* Wk  = (const float*)d_in[15];
    const float* bk  = (const float*)d_in[16];
    const float* Wv  = (const float*)d_in[17];
    const float* bv  = (const float*)d_in[18];
    const float* Wo  = (const float*)d_in[19];
    const float* bo  = (const float*)d_in[20];
    const float* Wg  = (const float*)d_in[21];
    const float* bg  = (const float*)d_in[22];
    const float* gamma1 = (const float*)d_in[23];
    const float* beta1  = (const float*)d_in[24];
    const float* gamma2 = (const float*)d_in[25];
    const float* beta2  = (const float*)d_in[26];

    k_proj<<<dim3(4, 128, 3), 256>>>(frontier, cross, mapf, Wf, bf, Wr, br, Wm, bm);
    k_h<<<dim3(2, 128), 256>>>(Wa1, ba1);
    k_aw<<<BSZ / 4, 128>>>(Wa2, ba2);
    k_qkv<<<dim3(4, 128, 9), 256>>>(Wq, bq, Wk, bk, Wv, bv);
    k_attn<<<BSZ, 128>>>();
    k_o<<<dim3(4, 384), 256>>>(Wo, bo);
    k_post1<<<BSZ, 128>>>(gamma1, beta1);
    k_gate<<<dim3(4, 128), 256>>>(Wg, bg);
    k_post2<<<BSZ, 128>>>(gamma2, beta2, (float*)d_out);
}

// round 3
// speedup vs baseline: 2.0244x; 2.0244x over previous
#include <cuda_runtime.h>
#include <cuda_bf16.h>
#include <stdint.h>
#include <math.h>

#define BSZ 16384
#define DM  512
#define NS  (BSZ*DM)
#define EPSLN 1e-6f

// ---------------- device-global scratch (no allocs allowed) ----------------
__device__ __nv_bfloat16 g_inh[3*NS], g_inl[3*NS];   // split inputs
__device__ __nv_bfloat16 g_ph [3*NS], g_pl [3*NS];   // split projections fp/rp/mp
__device__ __nv_bfloat16 g_chh[3*NS], g_chl[3*NS];   // split ctx (rows = B*3)
__device__ __nv_bfloat16 g_w2h[NS],   g_w2l[NS];     // split weighted
// transposed bf16 weights (layout [N, K] row-major)
#define OFF_WF  0
#define OFF_WR  262144
#define OFF_WM  524288
#define OFF_WQ  786432
#define OFF_WK  1048576
#define OFF_WV  1310720
#define OFF_WO  1572864
#define OFF_WG  1835008
#define OFF_WA1 2097152
#define WT_TOTAL (2097152 + 393216)
__device__ __nv_bfloat16 g_bwh[WT_TOTAL], g_bwl[WT_TOTAL];
// fp32 scratch
__device__ float g_fp[NS], g_rp[NS], g_mp[NS];
__device__ float g_h [BSZ*256];
__device__ float g_aw[BSZ*3];
__device__ float g_q [3*NS], g_k[3*NS], g_v[3*NS];
__device__ float g_o [3*NS];
__device__ float g_wt[NS], g_gl[NS];

// ---------------- PTX helpers ----------------
__device__ __forceinline__ uint32_t smem_u32(const void* p) {
    uint32_t a;
    asm("{ .reg .u64 t; cvta.to.shared.u64 t, %1; cvt.u32.u64 %0, t; }" : "=r"(a) : "l"(p));
    return a;
}
#define CP16(sm, gp) \
    asm volatile("cp.async.cg.shared.global [%0], [%1], 16;" :: "r"(sm), "l"(gp) : "memory")
#define CP_COMMIT() asm volatile("cp.async.commit_group;" ::: "memory")
#define CP_WAIT0()  asm volatile("cp.async.wait_group 0;" ::: "memory")
#define CP_WAIT1()  asm volatile("cp.async.wait_group 1;" ::: "memory")
#define LDSM4(d, a) \
    asm volatile("ldmatrix.sync.aligned.m8n8.x4.shared.b16 {%0,%1,%2,%3}, [%4];" \
        : "=r"((d)[0]), "=r"((d)[1]), "=r"((d)[2]), "=r"((d)[3]) : "r"(a))
#define LDSM2(d, a) \
    asm volatile("ldmatrix.sync.aligned.m8n8.x2.shared.b16 {%0,%1}, [%2];" \
        : "=r"((d)[0]), "=r"((d)[1]) : "r"(a))
__device__ __forceinline__ void mma16816(float* c, const uint32_t* a, const uint32_t* b) {
    asm volatile("mma.sync.aligned.m16n8k16.row.col.f32.bf16.bf16.f32 "
        "{%0,%1,%2,%3}, {%4,%5,%6,%7}, {%8,%9}, {%0,%1,%2,%3};"
        : "+f"(c[0]), "+f"(c[1]), "+f"(c[2]), "+f"(c[3])
        : "r"(a[0]), "r"(a[1]), "r"(a[2]), "r"(a[3]), "r"(b[0]), "r"(b[1]));
}

// ---------------- bf16-split tensor-core GEMM ----------------
// C[Mrows, N] = A x B^T, A[Mrows, K] (up to 3 row-matched K-segments),
// B[N, K] row-major, both as hi/lo bf16 splits. Tile 128x128x32,
// 256 thr / 8 warps, warp tile 64x32 (m16n8k16).
// smem per stage: 4 tiles of 128 rows x 40 elems (80B rows)
#define ROWB   80
#define S_AH   0
#define S_AL   10240
#define S_BH   20480
#define S_BL   30720
#define STAGEB 40960

template <int RELU, int WF32, int WBF16>
__device__ __forceinline__ void gemm_mma(
    const __nv_bfloat16* __restrict__ a_h0, const __nv_bfloat16* __restrict__ a_l0,
    const __nv_bfloat16* __restrict__ a_h1, const __nv_bfloat16* __restrict__ a_l1,
    const __nv_bfloat16* __restrict__ a_h2, const __nv_bfloat16* __restrict__ a_l2,
    int lda, int nchunks,
    const __nv_bfloat16* __restrict__ b_h, const __nv_bfloat16* __restrict__ b_l, int ldb,
    const float* __restrict__ bias,
    float* __restrict__ cf, int ldc,
    __nv_bfloat16* __restrict__ c_hi, __nv_bfloat16* __restrict__ c_lo, int ldcb)
{
    extern __shared__ char dsm[];
    const uint32_t smem = smem_u32(dsm);
    const int tid  = threadIdx.x;
    const int lane = tid & 31;
    const int warp = tid >> 5;
    const int wm = warp >> 2;   // 0..1  (64 rows each)
    const int wn = warp & 3;    // 0..3  (32 cols each)
    const int m0 = blockIdx.y * 128;
    const int n0 = blockIdx.x * 128;

    float acc[4][4][4];
#pragma unroll
    for (int i = 0; i < 4; i++)
#pragma unroll
        for (int j = 0; j < 4; j++)
#pragma unroll
            for (int k = 0; k < 4; k++) acc[i][j][k] = 0.f;

    const int row = tid >> 1;          // 0..127
    const int e0  = (tid & 1) * 16;    // elem offset of first 16B
    const uint32_t c0 = (tid & 1) * 32; // byte offset

    auto load_stage = [&](int st, int kc) {
        int seg = kc >> 4;
        const __nv_bfloat16* ah = (seg == 0) ? a_h0 : (seg == 1) ? a_h1 : a_h2;
        const __nv_bfloat16* al = (seg == 0) ? a_l0 : (seg == 1) ? a_l1 : a_l2;
        size_t aoff = (size_t)(m0 + row) * lda + (kc & 15) * 32 + e0;
        size_t boff = (size_t)(n0 + row) * ldb + kc * 32 + e0;
        uint32_t so = smem + st * STAGEB + row * ROWB + c0;
        CP16(so + S_AH,      ah + aoff);
        CP16(so + S_AH + 16, ah + aoff + 8);
        CP16(so + S_AL,      al + aoff);
        CP16(so + S_AL + 16, al + aoff + 8);
        CP16(so + S_BH,      b_h + boff);
        CP16(so + S_BH + 16, b_h + boff + 8);
        CP16(so + S_BL,      b_l + boff);
        CP16(so + S_BL + 16, b_l + boff + 8);
    };

    const uint32_t aRow = (wm * 64 + (lane & 15)) * ROWB + (lane >> 4) * 16;
    const uint32_t bRow = (wn * 32 + (lane & 7)) * ROWB + ((lane >> 3) & 1) * 16;

    auto compute_stage = [&](int st) {
        uint32_t base = smem + st * STAGEB;
#pragma unroll
        for (int k16 = 0; k16 < 2; k16++) {
            uint32_t ka = base + aRow + k16 * 32;
            uint32_t kb = base + bRow + k16 * 32;
            uint32_t a[4][4], bh[4][2], bl[4][2];
#pragma unroll
            for (int mt = 0; mt < 4; mt++) LDSM4(a[mt], ka + S_AH + mt * (16 * ROWB));
#pragma unroll
            for (int nt = 0; nt < 4; nt++) LDSM2(bh[nt], kb + S_BH + nt * (8 * ROWB));
#pragma unroll
            for (int nt = 0; nt < 4; nt++) LDSM2(bl[nt], kb + S_BL + nt * (8 * ROWB));
#pragma unroll
            for (int mt = 0; mt < 4; mt++)
#pragma unroll
                for (int nt = 0; nt < 4; nt++) mma16816(acc[mt][nt], a[mt], bh[nt]);
#pragma unroll
            for (int mt = 0; mt < 4; mt++)
#pragma unroll
                for (int nt = 0; nt < 4; nt++) mma16816(acc[mt][nt], a[mt], bl[nt]);
#pragma unroll
            for (int mt = 0; mt < 4; mt++) LDSM4(a[mt], ka + S_AL + mt * (16 * ROWB));
#pragma unroll
            for (int mt = 0; mt < 4; mt++)
#pragma unroll
                for (int nt = 0; nt < 4; nt++) mma16816(acc[mt][nt], a[mt], bh[nt]);
        }
    };

    load_stage(0, 0);
    CP_COMMIT();
    for (int kc = 0; kc < nchunks; kc++) {
        if (kc + 1 < nchunks) {
            load_stage((kc + 1) & 1, kc + 1);
            CP_COMMIT();
            CP_WAIT1();
        } else {
            CP_WAIT0();
        }
        __syncthreads();
        compute_stage(kc & 1);
        __syncthreads();
    }

    // epilogue
#pragma unroll
    for (int mt = 0; mt < 4; mt++) {
        int r0 = m0 + wm * 64 + mt * 16 + (lane >> 2);
        int r1 = r0 + 8;
#pragma unroll
        for (int nt = 0; nt < 4; nt++) {
            int cc = n0 + wn * 32 + nt * 8 + (lane & 3) * 2;
            float b0 = bias[cc], b1 = bias[cc + 1];
            float v00 = acc[mt][nt][0] + b0, v01 = acc[mt][nt][1] + b1;
            float v10 = acc[mt][nt][2] + b0, v11 = acc[mt][nt][3] + b1;
            if (RELU) {
                v00 = fmaxf(v00, 0.f); v01 = fmaxf(v01, 0.f);
                v10 = fmaxf(v10, 0.f); v11 = fmaxf(v11, 0.f);
            }
            if (WF32) {
                *(float2*)(cf + (size_t)r0 * ldc + cc) = make_float2(v00, v01);
                *(float2*)(cf + (size_t)r1 * ldc + cc) = make_float2(v10, v11);
            }
            if (WBF16) {
                __nv_bfloat16 h00 = __float2bfloat16(v00), h01 = __float2bfloat16(v01);
                __nv_bfloat16 h10 = __float2bfloat16(v10), h11 = __float2bfloat16(v11);
                __nv_bfloat162 p0, p1, l0, l1;
                p0.x = h00; p0.y = h01; p1.x = h10; p1.y = h11;
                l0.x = __float2bfloat16(v00 - __bfloat162float(h00));
                l0.y = __float2bfloat16(v01 - __bfloat162float(h01));
                l1.x = __float2bfloat16(v10 - __bfloat162float(h10));
                l1.y = __float2bfloat16(v11 - __bfloat162float(h11));
                *(__nv_bfloat162*)(c_hi + (size_t)r0 * ldcb + cc) = p0;
                *(__nv_bfloat162*)(c_hi + (size_t)r1 * ldcb + cc) = p1;
                *(__nv_bfloat162*)(c_lo + (size_t)r0 * ldcb + cc) = l0;
                *(__nv_bfloat162*)(c_lo + (size_t)r1 * ldcb + cc) = l1;
            }
        }
    }
}

// ---------------- GEMM wrapper kernels ----------------
__global__ __launch_bounds__(256, 1)
void k_gemm_proj(const float* __restrict__ bf, const float* __restrict__ br,
                 const float* __restrict__ bm)
{
    int z = blockIdx.z;
    const __nv_bfloat16* ah = g_inh + (size_t)z * NS;
    const __nv_bfloat16* al = g_inl + (size_t)z * NS;
    int off = (z == 0) ? OFF_WF : (z == 1) ? OFF_WR : OFF_WM;
    const float* bias = (z == 0) ? bf : (z == 1) ? br : bm;
    float* cf = (z == 0) ? g_fp : (z == 1) ? g_rp : g_mp;
    gemm_mma<0, 1, 1>(ah, al, ah, al, ah, al, 512, 16, g_bwh + off, g_bwl + off, 512, bias,
                      cf, 512, g_ph + (size_t)z * NS, g_pl + (size_t)z * NS, 512);
}

__global__ __launch_bounds__(256, 1)
void k_gemm_qkv(const float* __restrict__ bq, const float* __restrict__ bk,
                const float* __restrict__ bv)
{
    int z = blockIdx.z;
    int s = z / 3, w = z % 3;
    const __nv_bfloat16* ah = g_ph + (size_t)s * NS;
    const __nv_bfloat16* al = g_pl + (size_t)s * NS;
    int off = (w == 0) ? OFF_WQ : (w == 1) ? OFF_WK : OFF_WV;
    const float* bias = (w == 0) ? bq : (w == 1) ? bk : bv;
    float* cf = ((w == 0) ? g_q : (w == 1) ? g_k : g_v) + s * 512;
    gemm_mma<0, 1, 0>(ah, al, ah, al, ah, al, 512, 16, g_bwh + off, g_bwl + off, 512, bias,
                      cf, 1536, nullptr, nullptr, 0);
}

__global__ __launch_bounds__(256, 1)
void k_gemm_h(const float* __restrict__ ba1)
{
    gemm_mma<1, 1, 0>(g_ph, g_pl, g_ph + NS, g_pl + NS,
                      g_ph + 2 * (size_t)NS, g_pl + 2 * (size_t)NS,
                      512, 48, g_bwh + OFF_WA1, g_bwl + OFF_WA1, 1536, ba1,
                      g_h, 256, nullptr, nullptr, 0);
}

__global__ __launch_bounds__(256, 1)
void k_gemm_o(const float* __restrict__ bo)
{
    gemm_mma<0, 1, 0>(g_chh, g_chl, g_chh, g_chl, g_chh, g_chl, 512, 16,
                      g_bwh + OFF_WO, g_bwl + OFF_WO, 512, bo,
                      g_o, 512, nullptr, nullptr, 0);
}

__global__ __launch_bounds__(256, 1)
void k_gemm_gate(const float* __restrict__ bg)
{
    gemm_mma<0, 1, 0>(g_w2h, g_w2l, g_w2h, g_w2l, g_w2h, g_w2l, 512, 16,
                      g_bwh + OFF_WG, g_bwl + OFF_WG, 512, bg,
                      g_gl, 512, nullptr, nullptr, 0);
}

// ---------------- conversion kernels ----------------
__global__ __launch_bounds__(256)
void k_split(const float* __restrict__ x, __nv_bfloat16* __restrict__ h,
             __nv_bfloat16* __restrict__ l)
{
    int i = blockIdx.x * 256 + threadIdx.x;
    float4 v = ((const float4*)x)[i];
    __nv_bfloat16 h0 = __float2bfloat16(v.x), h1 = __float2bfloat16(v.y);
    __nv_bfloat16 h2 = __float2bfloat16(v.z), h3 = __float2bfloat16(v.w);
    __nv_bfloat162 a, b, c, d;
    a.x = h0; a.y = h1; b.x = h2; b.y = h3;
    c.x = __float2bfloat16(v.x - __bfloat162float(h0));
    c.y = __float2bfloat16(v.y - __bfloat162float(h1));
    d.x = __float2bfloat16(v.z - __bfloat162float(h2));
    d.y = __float2bfloat16(v.w - __bfloat162float(h3));
    ((__nv_bfloat162*)h)[2 * i] = a; ((__nv_bfloat162*)h)[2 * i + 1] = b;
    ((__nv_bfloat162*)l)[2 * i] = c; ((__nv_bfloat162*)l)[2 * i + 1] = d;
}

// transpose + split: W[R,C] fp32 -> out[C,R] bf16 hi/lo
__global__ __launch_bounds__(256)
void k_tw(const float* __restrict__ W, int R, int C,
          __nv_bfloat16* __restrict__ oh, __nv_bfloat16* __restrict__ ol)
{
    __shared__ float t[32][33];
    int bx = blockIdx.x * 32, by = blockIdx.y * 32;
    int x = threadIdx.x & 31, y = (threadIdx.x >> 5) * 4;
#pragma unroll
    for (int j = 0; j < 4; j++) t[y + j][x] = W[(size_t)(by + y + j) * C + bx + x];
    __syncthreads();
#pragma unroll
    for (int j = 0; j < 4; j++) {
        int n = bx + y + j, k = by + x;
        float v = t[x][y + j];
        __nv_bfloat16 h = __float2bfloat16(v);
        oh[(size_t)n * R + k] = h;
        ol[(size_t)n * R + k] = __float2bfloat16(v - __bfloat162float(h));
    }
}

// ---------------- small fused kernels ----------------
__global__ __launch_bounds__(128)
void k_aw(const float* __restrict__ Wa2, const float* __restrict__ ba2)
{
    int row = blockIdx.x * 4 + (threadIdx.x >> 5);
    int l = threadIdx.x & 31;
    const float* hr = g_h + (size_t)row * 256;
    float a0 = 0.f, a1 = 0.f, a2 = 0.f;
#pragma unroll
    for (int i = l; i < 256; i += 32) {
        float hv = hr[i];
        a0 = fmaf(hv, Wa2[i * 3 + 0], a0);
        a1 = fmaf(hv, Wa2[i * 3 + 1], a1);
        a2 = fmaf(hv, Wa2[i * 3 + 2], a2);
    }
#pragma unroll
    for (int off = 16; off; off >>= 1) {
        a0 += __shfl_xor_sync(0xffffffffu, a0, off);
        a1 += __shfl_xor_sync(0xffffffffu, a1, off);
        a2 += __shfl_xor_sync(0xffffffffu, a2, off);
    }
    if (l == 0) {
        a0 += ba2[0]; a1 += ba2[1]; a2 += ba2[2];
        float mx = fmaxf(a0, fmaxf(a1, a2));
        float e0 = expf(a0 - mx), e1 = expf(a1 - mx), e2 = expf(a2 - mx);
        float inv = 1.f / (e0 + e1 + e2);
        g_aw[row * 3 + 0] = e0 * inv;
        g_aw[row * 3 + 1] = e1 * inv;
        g_aw[row * 3 + 2] = e2 * inv;
    }
}

__device__ __forceinline__ float d4(float4 a, float4 b)
{ return a.x * b.x + a.y * b.y + a.z * b.z + a.w * b.w; }

__global__ __launch_bounds__(128)
void k_attn()
{
    int b = blockIdx.x;
    int h = threadIdx.x >> 5;
    int l = threadIdx.x & 31;
    size_t base = (size_t)b * 1536 + h * 128 + l * 4;
    float4 q0 = *(const float4*)&g_q[base];
    float4 q1 = *(const float4*)&g_q[base + 512];
    float4 q2 = *(const float4*)&g_q[base + 1024];
    float4 k0 = *(const float4*)&g_k[base];
    float4 k1 = *(const float4*)&g_k[base + 512];
    float4 k2 = *(const float4*)&g_k[base + 1024];
    float4 v0 = *(const float4*)&g_v[base];
    float4 v1 = *(const float4*)&g_v[base + 512];
    float4 v2 = *(const float4*)&g_v[base + 1024];

    float sc[3][3];
    sc[0][0] = d4(q0, k0); sc[0][1] = d4(q0, k1); sc[0][2] = d4(q0, k2);
    sc[1][0] = d4(q1, k0); sc[1][1] = d4(q1, k1); sc[1][2] = d4(q1, k2);
    sc[2][0] = d4(q2, k0); sc[2][1] = d4(q2, k1); sc[2][2] = d4(q2, k2);
#pragma unroll
    for (int qi = 0; qi < 3; qi++)
#pragma unroll
        for (int si = 0; si < 3; si++)
#pragma unroll
            for (int off = 16; off; off >>= 1)
                sc[qi][si] += __shfl_xor_sync(0xffffffffu, sc[qi][si], off);

    const float scale = 0.088388347648318447f;
#pragma unroll
    for (int qi = 0; qi < 3; qi++) {
        float s0 = sc[qi][0] * scale, s1 = sc[qi][1] * scale, s2 = sc[qi][2] * scale;
        float mx = fmaxf(s0, fmaxf(s1, s2));
        float e0 = expf(s0 - mx), e1 = expf(s1 - mx), e2 = expf(s2 - mx);
        float inv = 1.f / (e0 + e1 + e2);
        float a0 = e0 * inv, a1 = e1 * inv, a2 = e2 * inv;
        float4 c;
        c.x = a0 * v0.x + a1 * v1.x + a2 * v2.x;
        c.y = a0 * v0.y + a1 * v1.y + a2 * v2.y;
        c.z = a0 * v0.z + a1 * v1.z + a2 * v2.z;
        c.w = a0 * v0.w + a1 * v1.w + a2 * v2.w;
        size_t ob = base + (size_t)qi * 512;
        __nv_bfloat16 hx = __float2bfloat16(c.x), hy = __float2bfloat16(c.y);
        __nv_bfloat16 hz = __float2bfloat16(c.z), hw = __float2bfloat16(c.w);
        __nv_bfloat162 p0, p1, l0, l1;
        p0.x = hx; p0.y = hy; p1.x = hz; p1.y = hw;
        l0.x = __float2bfloat16(c.x - __bfloat162float(hx));
        l0.y = __float2bfloat16(c.y - __bfloat162float(hy));
        l1.x = __float2bfloat16(c.z - __bfloat162float(hz));
        l1.y = __float2bfloat16(c.w - __bfloat162float(hw));
        ((__nv_bfloat162*)&g_chh[ob])[0] = p0; ((__nv_bfloat162*)&g_chh[ob])[1] = p1;
        ((__nv_bfloat162*)&g_chl[ob])[0] = l0; ((__nv_bfloat162*)&g_chl[ob])[1] = l1;
    }
}

__device__ __forceinline__ void block_reduce2(float& s, float& q, float* ss, float* sq)
{
#pragma unroll
    for (int off = 16; off; off >>= 1) {
        s += __shfl_xor_sync(0xffffffffu, s, off);
        q += __shfl_xor_sync(0xffffffffu, q, off);
    }
    int w = threadIdx.x >> 5;
    if ((threadIdx.x & 31) == 0) { ss[w] = s; sq[w] = q; }
    __syncthreads();
    s = ss[0] + ss[1] + ss[2] + ss[3];
    q = sq[0] + sq[1] + sq[2] + sq[3];
    __syncthreads();
}

__global__ __launch_bounds__(128)
void k_post1(const float* __restrict__ gamma1, const float* __restrict__ beta1)
{
    __shared__ float ss[4], sq[4];
    int b = blockIdx.x;
    int d = threadIdx.x * 4;
    float aw0 = g_aw[b * 3 + 0], aw1 = g_aw[b * 3 + 1], aw2 = g_aw[b * 3 + 2];
    float4 gm = *(const float4*)&gamma1[d];
    float4 be = *(const float4*)&beta1[d];
    float4 wacc = make_float4(0.f, 0.f, 0.f, 0.f);
#pragma unroll
    for (int s = 0; s < 3; s++) {
        const float* X = (s == 0) ? g_fp : (s == 1) ? g_rp : g_mp;
        float4 xv = *(const float4*)&X[(size_t)b * 512 + d];
        float4 ov = *(const float4*)&g_o[((size_t)b * 3 + s) * 512 + d];
        float4 v;
        v.x = xv.x + ov.x; v.y = xv.y + ov.y; v.z = xv.z + ov.z; v.w = xv.w + ov.w;
        float lsum = v.x + v.y + v.z + v.w;
        float lsq  = v.x * v.x + v.y * v.y + v.z * v.z + v.w * v.w;
        block_reduce2(lsum, lsq, ss, sq);
        float mean = lsum * (1.f / 512.f);
        float var  = lsq * (1.f / 512.f) - mean * mean;
        float inv  = rsqrtf(var + EPSLN);
        float a = (s == 0) ? aw0 : (s == 1) ? aw1 : aw2;
        wacc.x += a * (gm.x * (v.x - mean) * inv + be.x);
        wacc.y += a * (gm.y * (v.y - mean) * inv + be.y);
        wacc.z += a * (gm.z * (v.z - mean) * inv + be.z);
        wacc.w += a * (gm.w * (v.w - mean) * inv + be.w);
    }
    size_t ob = (size_t)b * 512 + d;
    *(float4*)&g_wt[ob] = wacc;
    __nv_bfloat16 hx = __float2bfloat16(wacc.x), hy = __float2bfloat16(wacc.y);
    __nv_bfloat16 hz = __float2bfloat16(wacc.z), hw = __float2bfloat16(wacc.w);
    __nv_bfloat162 p0, p1, l0, l1;
    p0.x = hx; p0.y = hy; p1.x = hz; p1.y = hw;
    l0.x = __float2bfloat16(wacc.x - __bfloat162float(hx));
    l0.y = __float2bfloat16(wacc.y - __bfloat162float(hy));
    l1.x = __float2bfloat16(wacc.z - __bfloat162float(hz));
    l1.y = __float2bfloat16(wacc.w - __bfloat162float(hw));
    ((__nv_bfloat162*)&g_w2h[ob])[0] = p0; ((__nv_bfloat162*)&g_w2h[ob])[1] = p1;
    ((__nv_bfloat162*)&g_w2l[ob])[0] = l0; ((__nv_bfloat162*)&g_w2l[ob])[1] = l1;
}

__device__ __forceinline__ float sigm(float x) { return 1.f / (1.f + expf(-x)); }

__global__ __launch_bounds__(128)
void k_post2(const float* __restrict__ gamma2, const float* __restrict__ beta2,
             float* __restrict__ out)
{
    __shared__ float ss[4], sq[4];
    int b = blockIdx.x;
    int d = threadIdx.x * 4;
    float4 wv = *(const float4*)&g_wt[(size_t)b * 512 + d];
    float4 gl = *(const float4*)&g_gl[(size_t)b * 512 + d];
    float4 mp = *(const float4*)&g_mp[(size_t)b * 512 + d];
    float4 t;
    t.x = mp.x + sigm(gl.x) * wv.x;
    t.y = mp.y + sigm(gl.y) * wv.y;
    t.z = mp.z + sigm(gl.z) * wv.z;
    t.w = mp.w + sigm(gl.w) * wv.w;
    float lsum = t.x + t.y + t.z + t.w;
    float lsq  = t.x * t.x + t.y * t.y + t.z * t.z + t.w * t.w;
    block_reduce2(lsum, lsq, ss, sq);
    float mean = lsum * (1.f / 512.f);
    float var  = lsq * (1.f / 512.f) - mean * mean;
    float inv  = rsqrtf(var + EPSLN);
    float4 gm = *(const float4*)&gamma2[d];
    float4 be = *(const float4*)&beta2[d];
    float4 r;
    r.x = gm.x * (t.x - mean) * inv + be.x;
    r.y = gm.y * (t.y - mean) * inv + be.y;
    r.z = gm.z * (t.z - mean) * inv + be.z;
    r.w = gm.w * (t.w - mean) * inv + be.w;
    *(float4*)&out[(size_t)b * 512 + d] = r;
}

// ---------------- launch ----------------
extern "C" void kernel_launch(void* const* d_in, const int* in_sizes, int n_in,
                              void* d_out, int out_size)
{
    const float* frontier = (const float*)d_in[0];
    const float* cross    = (const float*)d_in[1];
    const float* mapf     = (const float*)d_in[2];
    const float* Wf  = (const float*)d_in[3];
    const float* bf  = (const float*)d_in[4];
    const float* Wr  = (const float*)d_in[5];
    const float* br  = (const float*)d_in[6];
    const float* Wm  = (const float*)d_in[7];
    const float* bm  = (const float*)d_in[8];
    const float* Wa1 = (const float*)d_in[9];
    const float* ba1 = (const float*)d_in[10];
    const float* Wa2 = (const float*)d_in[11];
    const float* ba2 = (const float*)d_in[12];
    const float* Wq  = (const float*)d_in[13];
    const float* bq  = (const float*)d_in[14];
    const float* Wk  = (const float*)d_in[15];
    const float* bk  = (const float*)d_in[16];
    const float* Wv  = (const float*)d_in[17];
    const float* bv  = (const float*)d_in[18];
    const float* Wo  = (const float*)d_in[19];
    const float* bo  = (const float*)d_in[20];
    const float* Wg  = (const float*)d_in[21];
    const float* bg  = (const float*)d_in[22];
    const float* gamma1 = (const float*)d_in[23];
    const float* beta1  = (const float*)d_in[24];
    const float* gamma2 = (const float*)d_in[25];
    const float* beta2  = (const float*)d_in[26];

    static int smem_set = 0;
    if (!smem_set) {
        cudaFuncSetAttribute(k_gemm_proj, cudaFuncAttributeMaxDynamicSharedMemorySize, 2 * STAGEB);
        cudaFuncSetAttribute(k_gemm_qkv,  cudaFuncAttributeMaxDynamicSharedMemorySize, 2 * STAGEB);
        cudaFuncSetAttribute(k_gemm_h,    cudaFuncAttributeMaxDynamicSharedMemorySize, 2 * STAGEB);
        cudaFuncSetAttribute(k_gemm_o,    cudaFuncAttributeMaxDynamicSharedMemorySize, 2 * STAGEB);
        cudaFuncSetAttribute(k_gemm_gate, cudaFuncAttributeMaxDynamicSharedMemorySize, 2 * STAGEB);
        smem_set = 1;
    }

    __nv_bfloat16 *inh, *inl, *bwh, *bwl;
    cudaGetSymbolAddress((void**)&inh, g_inh);
    cudaGetSymbolAddress((void**)&inl, g_inl);
    cudaGetSymbolAddress((void**)&bwh, g_bwh);
    cudaGetSymbolAddress((void**)&bwl, g_bwl);

    k_split<<<8192, 256>>>(frontier, inh + 0 * (size_t)NS, inl + 0 * (size_t)NS);
    k_split<<<8192, 256>>>(cross,    inh + 1 * (size_t)NS, inl + 1 * (size_t)NS);
    k_split<<<8192, 256>>>(mapf,     inh + 2 * (size_t)NS, inl + 2 * (size_t)NS);

    k_tw<<<dim3(16, 16), 256>>>(Wf, 512, 512, bwh + OFF_WF, bwl + OFF_WF);
    k_tw<<<dim3(16, 16), 256>>>(Wr, 512, 512, bwh + OFF_WR, bwl + OFF_WR);
    k_tw<<<dim3(16, 16), 256>>>(Wm, 512, 512, bwh + OFF_WM, bwl + OFF_WM);
    k_tw<<<dim3(16, 16), 256>>>(Wq, 512, 512, bwh + OFF_WQ, bwl + OFF_WQ);
    k_tw<<<dim3(16, 16), 256>>>(Wk, 512, 512, bwh + OFF_WK, bwl + OFF_WK);
    k_tw<<<dim3(16, 16), 256>>>(Wv, 512, 512, bwh + OFF_WV, bwl + OFF_WV);
    k_tw<<<dim3(16, 16), 256>>>(Wo, 512, 512, bwh + OFF_WO, bwl + OFF_WO);
    k_tw<<<dim3(16, 16), 256>>>(Wg, 512, 512, bwh + OFF_WG, bwl + OFF_WG);
    k_tw<<<dim3(8, 48), 256>>>(Wa1, 1536, 256, bwh + OFF_WA1, bwl + OFF_WA1);

    k_gemm_proj<<<dim3(4, 128, 3), 256, 2 * STAGEB>>>(bf, br, bm);
    k_gemm_h<<<dim3(2, 128, 1), 256, 2 * STAGEB>>>(ba1);
    k_aw<<<BSZ / 4, 128>>>(Wa2, ba2);
    k_gemm_qkv<<<dim3(4, 128, 9), 256, 2 * STAGEB>>>(bq, bk, bv);
    k_attn<<<BSZ, 128>>>();
    k_gemm_o<<<dim3(4, 384, 1), 256, 2 * STAGEB>>>(bo);
    k_post1<<<BSZ, 128>>>(gamma1, beta1);
    k_gemm_gate<<<dim3(4, 128, 1), 256, 2 * STAGEB>>>(bg);
    k_post2<<<BSZ, 128>>>(gamma2, beta2, (float*)d_out);
}

// round 4
// speedup vs baseline: 3.2060x; 1.5837x over previous
#include <cuda_runtime.h>
#include <cuda_fp16.h>
#include <stdint.h>
#include <math.h>

#define BSZ 16384
#define DM  512
#define NS  (BSZ*DM)
#define EPSLN 1e-6f

// ---------------- device-global scratch (no allocs allowed) ----------------
__device__ __half g_inh[3*NS], g_inl[3*NS];   // split inputs (fp16 hi/lo)
__device__ __half g_ph [3*NS], g_pl [3*NS];   // split projections fp/rp/mp
__device__ __half g_chh[3*NS], g_chl[3*NS];   // split ctx (rows = B*3)
__device__ __half g_w2h[NS],   g_w2l[NS];     // split weighted
// transposed fp16 weights (layout [N, K] row-major), hi only
#define OFF_WF  0
#define OFF_WR  262144
#define OFF_WM  524288
#define OFF_WQ  786432
#define OFF_WK  1048576
#define OFF_WV  1310720
#define OFF_WO  1572864
#define OFF_WG  1835008
#define OFF_WA1 2097152
#define WT_TOTAL (2097152 + 393216)
__device__ __half g_bwh[WT_TOTAL];
// fp32 scratch
__device__ float g_fp[NS], g_rp[NS], g_mp[NS];
__device__ float g_h [BSZ*256];
__device__ float g_aw[BSZ*3];
__device__ float g_q [3*NS], g_k[3*NS], g_v[3*NS];
__device__ float g_o [3*NS];
__device__ float g_wt[NS], g_gl[NS];

// ---------------- PTX helpers ----------------
__device__ __forceinline__ uint32_t smem_u32(const void* p) {
    uint32_t a;
    asm("{ .reg .u64 t; cvta.to.shared.u64 t, %1; cvt.u32.u64 %0, t; }" : "=r"(a) : "l"(p));
    return a;
}
#define CP16(sm, gp) \
    asm volatile("cp.async.cg.shared.global [%0], [%1], 16;" :: "r"(sm), "l"(gp) : "memory")
#define CP_COMMIT() asm volatile("cp.async.commit_group;" ::: "memory")
#define CP_WAIT1()  asm volatile("cp.async.wait_group 1;" ::: "memory")
#define LDSM4(d, a) \
    asm volatile("ldmatrix.sync.aligned.m8n8.x4.shared.b16 {%0,%1,%2,%3}, [%4];" \
        : "=r"((d)[0]), "=r"((d)[1]), "=r"((d)[2]), "=r"((d)[3]) : "r"(a))
#define LDSM2(d, a) \
    asm volatile("ldmatrix.sync.aligned.m8n8.x2.shared.b16 {%0,%1}, [%2];" \
        : "=r"((d)[0]), "=r"((d)[1]) : "r"(a))
__device__ __forceinline__ void mma16816(float* c, const uint32_t* a, const uint32_t* b) {
    asm volatile("mma.sync.aligned.m16n8k16.row.col.f32.f16.f16.f32 "
        "{%0,%1,%2,%3}, {%4,%5,%6,%7}, {%8,%9}, {%0,%1,%2,%3};"
        : "+f"(c[0]), "+f"(c[1]), "+f"(c[2]), "+f"(c[3])
        : "r"(a[0]), "r"(a[1]), "r"(a[2]), "r"(a[3]), "r"(b[0]), "r"(b[1]));
}

// ---------------- fp16 2-term split tensor-core GEMM ----------------
// C = (A_hi + A_lo) x B_hi^T.  A[Mrows,K] (up to 3 row-matched K-segments) as
// fp16 hi/lo, B[N,K] row-major fp16. Tile 128x128x32, 256 thr, warp 64x32.
// 3-stage cp.async pipeline, one __syncthreads per chunk.
#define ROWB   80
#define S_AH   0
#define S_AL   10240
#define S_BH   20480
#define STAGEB 30720
#define NSTG   3

template <int RELU, int WF32, int WF16>
__device__ __forceinline__ void gemm_mma(
    const __half* __restrict__ a_h0, const __half* __restrict__ a_l0,
    const __half* __restrict__ a_h1, const __half* __restrict__ a_l1,
    const __half* __restrict__ a_h2, const __half* __restrict__ a_l2,
    int lda, int nchunks,
    const __half* __restrict__ b_h, int ldb,
    const float* __restrict__ bias,
    float* __restrict__ cf, int ldc,
    __half* __restrict__ c_hi, __half* __restrict__ c_lo, int ldcb)
{
    extern __shared__ char dsm[];
    const uint32_t smem = smem_u32(dsm);
    const int tid  = threadIdx.x;
    const int lane = tid & 31;
    const int warp = tid >> 5;
    const int wm = warp >> 2;   // 0..1 (64 rows)
    const int wn = warp & 3;    // 0..3 (32 cols)
    const int m0 = blockIdx.y * 128;
    const int n0 = blockIdx.x * 128;

    float acc[4][4][4];
#pragma unroll
    for (int i = 0; i < 4; i++)
#pragma unroll
        for (int j = 0; j < 4; j++)
#pragma unroll
            for (int k = 0; k < 4; k++) acc[i][j][k] = 0.f;

    const int row = tid >> 1;
    const int e0  = (tid & 1) * 16;          // fp16 elems
    const uint32_t c0 = (tid & 1) * 32;      // bytes

    auto load_stage = [&](int st, int kc) {
        int seg = kc >> 4;
        const __half* ah = (seg == 0) ? a_h0 : (seg == 1) ? a_h1 : a_h2;
        const __half* al = (seg == 0) ? a_l0 : (seg == 1) ? a_l1 : a_l2;
        size_t aoff = (size_t)(m0 + row) * lda + (kc & 15) * 32 + e0;
        size_t boff = (size_t)(n0 + row) * ldb + kc * 32 + e0;
        uint32_t so = smem + st * STAGEB + row * ROWB + c0;
        CP16(so + S_AH,      ah + aoff);
        CP16(so + S_AH + 16, ah + aoff + 8);
        CP16(so + S_AL,      al + aoff);
        CP16(so + S_AL + 16, al + aoff + 8);
        CP16(so + S_BH,      b_h + boff);
        CP16(so + S_BH + 16, b_h + boff + 8);
    };

    const uint32_t aRow = (wm * 64 + (lane & 15)) * ROWB + (lane >> 4) * 16;
    const uint32_t bRow = (wn * 32 + (lane & 7)) * ROWB + ((lane >> 3) & 1) * 16;

    auto compute_stage = [&](int st) {
        uint32_t base = smem + st * STAGEB;
#pragma unroll
        for (int k16 = 0; k16 < 2; k16++) {
            uint32_t ka = base + aRow + k16 * 32;
            uint32_t kb = base + bRow + k16 * 32;
            uint32_t a[4][4], b[4][2];
#pragma unroll
            for (int nt = 0; nt < 4; nt++) LDSM2(b[nt], kb + S_BH + nt * (8 * ROWB));
#pragma unroll
            for (int mt = 0; mt < 4; mt++) LDSM4(a[mt], ka + S_AH + mt * (16 * ROWB));
#pragma unroll
            for (int mt = 0; mt < 4; mt++)
#pragma unroll
                for (int nt = 0; nt < 4; nt++) mma16816(acc[mt][nt], a[mt], b[nt]);
#pragma unroll
            for (int mt = 0; mt < 4; mt++) LDSM4(a[mt], ka + S_AL + mt * (16 * ROWB));
#pragma unroll
            for (int mt = 0; mt < 4; mt++)
#pragma unroll
                for (int nt = 0; nt < 4; nt++) mma16816(acc[mt][nt], a[mt], b[nt]);
        }
    };

    load_stage(0, 0); CP_COMMIT();
    load_stage(1, 1); CP_COMMIT();
    for (int kc = 0; kc < nchunks; kc++) {
        CP_WAIT1();
        __syncthreads();
        if (kc + 2 < nchunks) load_stage((kc + 2) % NSTG, kc + 2);
        CP_COMMIT();
        compute_stage(kc % NSTG);
    }

    // epilogue
#pragma unroll
    for (int mt = 0; mt < 4; mt++) {
        int r0 = m0 + wm * 64 + mt * 16 + (lane >> 2);
        int r1 = r0 + 8;
#pragma unroll
        for (int nt = 0; nt < 4; nt++) {
            int cc = n0 + wn * 32 + nt * 8 + (lane & 3) * 2;
            float b0 = bias[cc], b1 = bias[cc + 1];
            float v00 = acc[mt][nt][0] + b0, v01 = acc[mt][nt][1] + b1;
            float v10 = acc[mt][nt][2] + b0, v11 = acc[mt][nt][3] + b1;
            if (RELU) {
                v00 = fmaxf(v00, 0.f); v01 = fmaxf(v01, 0.f);
                v10 = fmaxf(v10, 0.f); v11 = fmaxf(v11, 0.f);
            }
            if (WF32) {
                *(float2*)(cf + (size_t)r0 * ldc + cc) = make_float2(v00, v01);
                *(float2*)(cf + (size_t)r1 * ldc + cc) = make_float2(v10, v11);
            }
            if (WF16) {
                __half h00 = __float2half_rn(v00), h01 = __float2half_rn(v01);
                __half h10 = __float2half_rn(v10), h11 = __float2half_rn(v11);
                __half2 p0, p1, l0, l1;
                p0.x = h00; p0.y = h01; p1.x = h10; p1.y = h11;
                l0.x = __float2half_rn(v00 - __half2float(h00));
                l0.y = __float2half_rn(v01 - __half2float(h01));
                l1.x = __float2half_rn(v10 - __half2float(h10));
                l1.y = __float2half_rn(v11 - __half2float(h11));
                *(__half2*)(c_hi + (size_t)r0 * ldcb + cc) = p0;
                *(__half2*)(c_hi + (size_t)r1 * ldcb + cc) = p1;
                *(__half2*)(c_lo + (size_t)r0 * ldcb + cc) = l0;
                *(__half2*)(c_lo + (size_t)r1 * ldcb + cc) = l1;
            }
        }
    }
}

// ---------------- GEMM wrapper kernels ----------------
__global__ __launch_bounds__(256, 2)
void k_gemm_proj(const float* __restrict__ bf, const float* __restrict__ br,
                 const float* __restrict__ bm)
{
    int z = blockIdx.z;
    const __half* ah = g_inh + (size_t)z * NS;
    const __half* al = g_inl + (size_t)z * NS;
    int off = (z == 0) ? OFF_WF : (z == 1) ? OFF_WR : OFF_WM;
    const float* bias = (z == 0) ? bf : (z == 1) ? br : bm;
    float* cf = (z == 0) ? g_fp : (z == 1) ? g_rp : g_mp;
    gemm_mma<0, 1, 1>(ah, al, ah, al, ah, al, 512, 16, g_bwh + off, 512, bias,
                      cf, 512, g_ph + (size_t)z * NS, g_pl + (size_t)z * NS, 512);
}

__global__ __launch_bounds__(256, 2)
void k_gemm_qkv(const float* __restrict__ bq, const float* __restrict__ bk,
                const float* __restrict__ bv)
{
    int z = blockIdx.z;
    int s = z / 3, w = z % 3;
    const __half* ah = g_ph + (size_t)s * NS;
    const __half* al = g_pl + (size_t)s * NS;
    int off = (w == 0) ? OFF_WQ : (w == 1) ? OFF_WK : OFF_WV;
    const float* bias = (w == 0) ? bq : (w == 1) ? bk : bv;
    float* cf = ((w == 0) ? g_q : (w == 1) ? g_k : g_v) + s * 512;
    gemm_mma<0, 1, 0>(ah, al, ah, al, ah, al, 512, 16, g_bwh + off, 512, bias,
                      cf, 1536, nullptr, nullptr, 0);
}

__global__ __launch_bounds__(256, 2)
void k_gemm_h(const float* __restrict__ ba1)
{
    gemm_mma<1, 1, 0>(g_ph, g_pl, g_ph + NS, g_pl + NS,
                      g_ph + 2 * (size_t)NS, g_pl + 2 * (size_t)NS,
                      512, 48, g_bwh + OFF_WA1, 1536, ba1,
                      g_h, 256, nullptr, nullptr, 0);
}

__global__ __launch_bounds__(256, 2)
void k_gemm_o(const float* __restrict__ bo)
{
    gemm_mma<0, 1, 0>(g_chh, g_chl, g_chh, g_chl, g_chh, g_chl, 512, 16,
                      g_bwh + OFF_WO, 512, bo,
                      g_o, 512, nullptr, nullptr, 0);
}

__global__ __launch_bounds__(256, 2)
void k_gemm_gate(const float* __restrict__ bg)
{
    gemm_mma<0, 1, 0>(g_w2h, g_w2l, g_w2h, g_w2l, g_w2h, g_w2l, 512, 16,
                      g_bwh + OFF_WG, 512, bg,
                      g_gl, 512, nullptr, nullptr, 0);
}

// ---------------- conversion kernels ----------------
__global__ __launch_bounds__(256)
void k_split3(const float* __restrict__ x0, const float* __restrict__ x1,
              const float* __restrict__ x2)
{
    int z = blockIdx.z;
    const float* x = (z == 0) ? x0 : (z == 1) ? x1 : x2;
    __half* h = g_inh + (size_t)z * NS;
    __half* l = g_inl + (size_t)z * NS;
    int i = blockIdx.x * 256 + threadIdx.x;
    float4 v = ((const float4*)x)[i];
    __half h0 = __float2half_rn(v.x), h1 = __float2half_rn(v.y);
    __half h2 = __float2half_rn(v.z), h3 = __float2half_rn(v.w);
    __half2 a, b, c, d;
    a.x = h0; a.y = h1; b.x = h2; b.y = h3;
    c.x = __float2half_rn(v.x - __half2float(h0));
    c.y = __float2half_rn(v.y - __half2float(h1));
    d.x = __float2half_rn(v.z - __half2float(h2));
    d.y = __float2half_rn(v.w - __half2float(h3));
    ((__half2*)h)[2 * i] = a; ((__half2*)h)[2 * i + 1] = b;
    ((__half2*)l)[2 * i] = c; ((__half2*)l)[2 * i + 1] = d;
}

// transpose: W[R,C] fp32 -> out[C,R] fp16 (hi only)
__global__ __launch_bounds__(256)
void k_tw(const float* __restrict__ W, int R, int C, __half* __restrict__ oh)
{
    __shared__ float t[32][33];
    int bx = blockIdx.x * 32, by = blockIdx.y * 32;
    int x = threadIdx.x & 31, y = (threadIdx.x >> 5) * 4;
#pragma unroll
    for (int j = 0; j < 4; j++) t[y + j][x] = W[(size_t)(by + y + j) * C + bx + x];
    __syncthreads();
#pragma unroll
    for (int j = 0; j < 4; j++) {
        int n = bx + y + j, k = by + x;
        oh[(size_t)n * R + k] = __float2half_rn(t[x][y + j]);
    }
}

// ---------------- small fused kernels ----------------
__global__ __launch_bounds__(128)
void k_aw(const float* __restrict__ Wa2, const float* __restrict__ ba2)
{
    int row = blockIdx.x * 4 + (threadIdx.x >> 5);
    int l = threadIdx.x & 31;
    const float* hr = g_h + (size_t)row * 256;
    float a0 = 0.f, a1 = 0.f, a2 = 0.f;
#pragma unroll
    for (int i = l; i < 256; i += 32) {
        float hv = hr[i];
        a0 = fmaf(hv, Wa2[i * 3 + 0], a0);
        a1 = fmaf(hv, Wa2[i * 3 + 1], a1);
        a2 = fmaf(hv, Wa2[i * 3 + 2], a2);
    }
#pragma unroll
    for (int off = 16; off; off >>= 1) {
        a0 += __shfl_xor_sync(0xffffffffu, a0, off);
        a1 += __shfl_xor_sync(0xffffffffu, a1, off);
        a2 += __shfl_xor_sync(0xffffffffu, a2, off);
    }
    if (l == 0) {
        a0 += ba2[0]; a1 += ba2[1]; a2 += ba2[2];
        float mx = fmaxf(a0, fmaxf(a1, a2));
        float e0 = expf(a0 - mx), e1 = expf(a1 - mx), e2 = expf(a2 - mx);
        float inv = 1.f / (e0 + e1 + e2);
        g_aw[row * 3 + 0] = e0 * inv;
        g_aw[row * 3 + 1] = e1 * inv;
        g_aw[row * 3 + 2] = e2 * inv;
    }
}

__device__ __forceinline__ float d4(float4 a, float4 b)
{ return a.x * b.x + a.y * b.y + a.z * b.z + a.w * b.w; }

__global__ __launch_bounds__(128)
void k_attn()
{
    int b = blockIdx.x;
    int h = threadIdx.x >> 5;
    int l = threadIdx.x & 31;
    size_t base = (size_t)b * 1536 + h * 128 + l * 4;
    float4 q0 = *(const float4*)&g_q[base];
    float4 q1 = *(const float4*)&g_q[base + 512];
    float4 q2 = *(const float4*)&g_q[base + 1024];
    float4 k0 = *(const float4*)&g_k[base];
    float4 k1 = *(const float4*)&g_k[base + 512];
    float4 k2 = *(const float4*)&g_k[base + 1024];
    float4 v0 = *(const float4*)&g_v[base];
    float4 v1 = *(const float4*)&g_v[base + 512];
    float4 v2 = *(const float4*)&g_v[base + 1024];

    float sc[3][3];
    sc[0][0] = d4(q0, k0); sc[0][1] = d4(q0, k1); sc[0][2] = d4(q0, k2);
    sc[1][0] = d4(q1, k0); sc[1][1] = d4(q1, k1); sc[1][2] = d4(q1, k2);
    sc[2][0] = d4(q2, k0); sc[2][1] = d4(q2, k1); sc[2][2] = d4(q2, k2);
#pragma unroll
    for (int qi = 0; qi < 3; qi++)
#pragma unroll
        for (int si = 0; si < 3; si++)
#pragma unroll
            for (int off = 16; off; off >>= 1)
                sc[qi][si] += __shfl_xor_sync(0xffffffffu, sc[qi][si], off);

    const float scale = 0.088388347648318447f;
#pragma unroll
    for (int qi = 0; qi < 3; qi++) {
        float s0 = sc[qi][0] * scale, s1 = sc[qi][1] * scale, s2 = sc[qi][2] * scale;
        float mx = fmaxf(s0, fmaxf(s1, s2));
        float e0 = expf(s0 - mx), e1 = expf(s1 - mx), e2 = expf(s2 - mx);
        float inv = 1.f / (e0 + e1 + e2);
        float a0 = e0 * inv, a1 = e1 * inv, a2 = e2 * inv;
        float4 c;
        c.x = a0 * v0.x + a1 * v1.x + a2 * v2.x;
        c.y = a0 * v0.y + a1 * v1.y + a2 * v2.y;
        c.z = a0 * v0.z + a1 * v1.z + a2 * v2.z;
        c.w = a0 * v0.w + a1 * v1.w + a2 * v2.w;
        size_t ob = base + (size_t)qi * 512;
        __half hx = __float2half_rn(c.x), hy = __float2half_rn(c.y);
        __half hz = __float2half_rn(c.z), hw = __float2half_rn(c.w);
        __half2 p0, p1, l0, l1;
        p0.x = hx; p0.y = hy; p1.x = hz; p1.y = hw;
        l0.x = __float2half_rn(c.x - __half2float(hx));
        l0.y = __float2half_rn(c.y - __half2float(hy));
        l1.x = __float2half_rn(c.z - __half2float(hz));
        l1.y = __float2half_rn(c.w - __half2float(hw));
        ((__half2*)&g_chh[ob])[0] = p0; ((__half2*)&g_chh[ob])[1] = p1;
        ((__half2*)&g_chl[ob])[0] = l0; ((__half2*)&g_chl[ob])[1] = l1;
    }
}

__device__ __forceinline__ void block_reduce2(float& s, float& q, float* ss, float* sq)
{
#pragma unroll
    for (int off = 16; off; off >>= 1) {
        s += __shfl_xor_sync(0xffffffffu, s, off);
        q += __shfl_xor_sync(0xffffffffu, q, off);
    }
    int w = threadIdx.x >> 5;
    if ((threadIdx.x & 31) == 0) { ss[w] = s; sq[w] = q; }
    __syncthreads();
    s = ss[0] + ss[1] + ss[2] + ss[3];
    q = sq[0] + sq[1] + sq[2] + sq[3];
    __syncthreads();
}

__global__ __launch_bounds__(128)
void k_post1(const float* __restrict__ gamma1, const float* __restrict__ beta1)
{
    __shared__ float ss[4], sq[4];
    int b = blockIdx.x;
    int d = threadIdx.x * 4;
    float aw0 = g_aw[b * 3 + 0], aw1 = g_aw[b * 3 + 1], aw2 = g_aw[b * 3 + 2];
    float4 gm = *(const float4*)&gamma1[d];
    float4 be = *(const float4*)&beta1[d];
    float4 wacc = make_float4(0.f, 0.f, 0.f, 0.f);
#pragma unroll
    for (int s = 0; s < 3; s++) {
        const float* X = (s == 0) ? g_fp : (s == 1) ? g_rp : g_mp;
        float4 xv = *(const float4*)&X[(size_t)b * 512 + d];
        float4 ov = *(const float4*)&g_o[((size_t)b * 3 + s) * 512 + d];
        float4 v;
        v.x = xv.x + ov.x; v.y = xv.y + ov.y; v.z = xv.z + ov.z; v.w = xv.w + ov.w;
        float lsum = v.x + v.y + v.z + v.w;
        float lsq  = v.x * v.x + v.y * v.y + v.z * v.z + v.w * v.w;
        block_reduce2(lsum, lsq, ss, sq);
        float mean = lsum * (1.f / 512.f);
        float var  = lsq * (1.f / 512.f) - mean * mean;
        float inv  = rsqrtf(var + EPSLN);
        float a = (s == 0) ? aw0 : (s == 1) ? aw1 : aw2;
        wacc.x += a * (gm.x * (v.x - mean) * inv + be.x);
        wacc.y += a * (gm.y * (v.y - mean) * inv + be.y);
        wacc.z += a * (gm.z * (v.z - mean) * inv + be.z);
        wacc.w += a * (gm.w * (v.w - mean) * inv + be.w);
    }
    size_t ob = (size_t)b * 512 + d;
    *(float4*)&g_wt[ob] = wacc;
    __half hx = __float2half_rn(wacc.x), hy = __float2half_rn(wacc.y);
    __half hz = __float2half_rn(wacc.z), hw = __float2half_rn(wacc.w);
    __half2 p0, p1, l0, l1;
    p0.x = hx; p0.y = hy; p1.x = hz; p1.y = hw;
    l0.x = __float2half_rn(wacc.x - __half2float(hx));
    l0.y = __float2half_rn(wacc.y - __half2float(hy));
    l1.x = __float2half_rn(wacc.z - __half2float(hz));
    l1.y = __float2half_rn(wacc.w - __half2float(hw));
    ((__half2*)&g_w2h[ob])[0] = p0; ((__half2*)&g_w2h[ob])[1] = p1;
    ((__half2*)&g_w2l[ob])[0] = l0; ((__half2*)&g_w2l[ob])[1] = l1;
}

__device__ __forceinline__ float sigm(float x) { return 1.f / (1.f + expf(-x)); }

__global__ __launch_bounds__(128)
void k_post2(const float* __restrict__ gamma2, const float* __restrict__ beta2,
             float* __restrict__ out)
{
    __shared__ float ss[4], sq[4];
    int b = blockIdx.x;
    int d = threadIdx.x * 4;
    float4 wv = *(const float4*)&g_wt[(size_t)b * 512 + d];
    float4 gl = *(const float4*)&g_gl[(size_t)b * 512 + d];
    float4 mp = *(const float4*)&g_mp[(size_t)b * 512 + d];
    float4 t;
    t.x = mp.x + sigm(gl.x) * wv.x;
    t.y = mp.y + sigm(gl.y) * wv.y;
    t.z = mp.z + sigm(gl.z) * wv.z;
    t.w = mp.w + sigm(gl.w) * wv.w;
    float lsum = t.x + t.y + t.z + t.w;
    float lsq  = t.x * t.x + t.y * t.y + t.z * t.z + t.w * t.w;
    block_reduce2(lsum, lsq, ss, sq);
    float mean = lsum * (1.f / 512.f);
    float var  = lsq * (1.f / 512.f) - mean * mean;
    float inv  = rsqrtf(var + EPSLN);
    float4 gm = *(const float4*)&gamma2[d];
    float4 be = *(const float4*)&beta2[d];
    float4 r;
    r.x = gm.x * (t.x - mean) * inv + be.x;
    r.y = gm.y * (t.y - mean) * inv + be.y;
    r.z = gm.z * (t.z - mean) * inv + be.z;
    r.w = gm.w * (t.w - mean) * inv + be.w;
    *(float4*)&out[(size_t)b * 512 + d] = r;
}

// ---------------- launch ----------------
extern "C" void kernel_launch(void* const* d_in, const int* in_sizes, int n_in,
                              void* d_out, int out_size)
{
    const float* frontier = (const float*)d_in[0];
    const float* cross    = (const float*)d_in[1];
    const float* mapf     = (const float*)d_in[2];
    const float* Wf  = (const float*)d_in[3];
    const float* bf  = (const float*)d_in[4];
    const float* Wr  = (const float*)d_in[5];
    const float* br  = (const float*)d_in[6];
    const float* Wm  = (const float*)d_in[7];
    const float* bm  = (const float*)d_in[8];
    const float* Wa1 = (const float*)d_in[9];
    const float* ba1 = (const float*)d_in[10];
    const float* Wa2 = (const float*)d_in[11];
    const float* ba2 = (const float*)d_in[12];
    const float* Wq  = (const float*)d_in[13];
    const float* bq  = (const float*)d_in[14];
    const float* Wk  = (const float*)d_in[15];
    const float* bk  = (const float*)d_in[16];
    const float* Wv  = (const float*)d_in[17];
    const float* bv  = (const float*)d_in[18];
    const float* Wo  = (const float*)d_in[19];
    const float* bo  = (const float*)d_in[20];
    const float* Wg  = (const float*)d_in[21];
    const float* bg  = (const float*)d_in[22];
    const float* gamma1 = (const float*)d_in[23];
    const float* beta1  = (const float*)d_in[24];
    const float* gamma2 = (const float*)d_in[25];
    const float* beta2  = (const float*)d_in[26];

    cudaFuncSetAttribute(k_gemm_proj, cudaFuncAttributeMaxDynamicSharedMemorySize, NSTG * STAGEB);
    cudaFuncSetAttribute(k_gemm_qkv,  cudaFuncAttributeMaxDynamicSharedMemorySize, NSTG * STAGEB);
    cudaFuncSetAttribute(k_gemm_h,    cudaFuncAttributeMaxDynamicSharedMemorySize, NSTG * STAGEB);
    cudaFuncSetAttribute(k_gemm_o,    cudaFuncAttributeMaxDynamicSharedMemorySize, NSTG * STAGEB);
    cudaFuncSetAttribute(k_gemm_gate, cudaFuncAttributeMaxDynamicSharedMemorySize, NSTG * STAGEB);

    __half* bwh;
    cudaGetSymbolAddress((void**)&bwh, g_bwh);

    k_split3<<<dim3(8192, 1, 3), 256>>>(frontier, cross, mapf);

    k_tw<<<dim3(16, 16), 256>>>(Wf, 512, 512, bwh + OFF_WF);
    k_tw<<<dim3(16, 16), 256>>>(Wr, 512, 512, bwh + OFF_WR);
    k_tw<<<dim3(16, 16), 256>>>(Wm, 512, 512, bwh + OFF_WM);
    k_tw<<<dim3(16, 16), 256>>>(Wq, 512, 512, bwh + OFF_WQ);
    k_tw<<<dim3(16, 16), 256>>>(Wk, 512, 512, bwh + OFF_WK);
    k_tw<<<dim3(16, 16), 256>>>(Wv, 512, 512, bwh + OFF_WV);
    k_tw<<<dim3(16, 16), 256>>>(Wo, 512, 512, bwh + OFF_WO);
    k_tw<<<dim3(16, 16), 256>>>(Wg, 512, 512, bwh + OFF_WG);
    k_tw<<<dim3(8, 48), 256>>>(Wa1, 1536, 256, bwh + OFF_WA1);

    k_gemm_proj<<<dim3(4, 128, 3), 256, NSTG * STAGEB>>>(bf, br, bm);
    k_gemm_h<<<dim3(2, 128, 1), 256, NSTG * STAGEB>>>(ba1);
    k_aw<<<BSZ / 4, 128>>>(Wa2, ba2);
    k_gemm_qkv<<<dim3(4, 128, 9), 256, NSTG * STAGEB>>>(bq, bk, bv);
    k_attn<<<BSZ, 128>>>();
    k_gemm_o<<<dim3(4, 384, 1), 256, NSTG * STAGEB>>>(bo);
    k_post1<<<BSZ, 128>>>(gamma1, beta1);
    k_gemm_gate<<<dim3(4, 128, 1), 256, NSTG * STAGEB>>>(bg);
    k_post2<<<BSZ, 128>>>(gamma2, beta2, (float*)d_out);
}